// round 1
// baseline (speedup 1.0000x reference)
#include <cuda_runtime.h>
#include <math.h>

// Problem constants
#define EDIM 1024
#define BATCH 2
#define SEQ 2048
#define NHEADS 16
#define HDIM 64
#define MROWS (BATCH * SEQ)          // 4096
#define INV_SCALE 0.125f             // 1/sqrt(64)

// Scratch (allocation-free: static __device__ globals)
__device__ float g_Q[MROWS * EDIM];
__device__ float g_K[MROWS * EDIM];
__device__ float g_V[MROWS * EDIM];
__device__ float g_O[MROWS * EDIM];

// ---------------------------------------------------------------------------
// SGEMM:  C[M,N] = A[M,K] @ W[N,K]^T   (both operands K-contiguous, row-major)
// 128x128 CTA tile, BK=8, 256 threads, 8x8 register tile per thread.
// ---------------------------------------------------------------------------
#define BM 128
#define BN 128
#define BKK 8

__global__ __launch_bounds__(256) void sgemm_nt(
    const float* __restrict__ A,
    const float* __restrict__ W,
    float* __restrict__ C,
    int M, int N, int K)
{
    __shared__ float As[BKK][BM + 4];
    __shared__ float Bs[BKK][BN + 4];

    const int tid = threadIdx.x;
    const int bm = blockIdx.y * BM;
    const int bn = blockIdx.x * BN;

    const int tr = (tid >> 4) * 8;   // 0..120
    const int tc = (tid & 15) * 8;   // 0..120

    const int loadRow = tid >> 1;         // 0..127
    const int loadCol = (tid & 1) * 4;    // 0 or 4

    float acc[8][8];
#pragma unroll
    for (int i = 0; i < 8; i++)
#pragma unroll
        for (int j = 0; j < 8; j++) acc[i][j] = 0.f;

    const float* Aptr = A + (size_t)(bm + loadRow) * K + loadCol;
    const float* Wptr = W + (size_t)(bn + loadRow) * K + loadCol;

    for (int k0 = 0; k0 < K; k0 += BKK) {
        float4 a4 = *(const float4*)(Aptr + k0);
        float4 w4 = *(const float4*)(Wptr + k0);
        As[loadCol + 0][loadRow] = a4.x;
        As[loadCol + 1][loadRow] = a4.y;
        As[loadCol + 2][loadRow] = a4.z;
        As[loadCol + 3][loadRow] = a4.w;
        Bs[loadCol + 0][loadRow] = w4.x;
        Bs[loadCol + 1][loadRow] = w4.y;
        Bs[loadCol + 2][loadRow] = w4.z;
        Bs[loadCol + 3][loadRow] = w4.w;
        __syncthreads();

#pragma unroll
        for (int k = 0; k < BKK; k++) {
            float ar[8], br[8];
#pragma unroll
            for (int i = 0; i < 8; i++) ar[i] = As[k][tr + i];
#pragma unroll
            for (int j = 0; j < 8; j++) br[j] = Bs[k][tc + j];
#pragma unroll
            for (int i = 0; i < 8; i++)
#pragma unroll
                for (int j = 0; j < 8; j++)
                    acc[i][j] = fmaf(ar[i], br[j], acc[i][j]);
        }
        __syncthreads();
    }

#pragma unroll
    for (int i = 0; i < 8; i++) {
        float* crow = C + (size_t)(bm + tr + i) * N + bn + tc;
        float4 o0 = make_float4(acc[i][0], acc[i][1], acc[i][2], acc[i][3]);
        float4 o1 = make_float4(acc[i][4], acc[i][5], acc[i][6], acc[i][7]);
        *(float4*)(crow + 0) = o0;
        *(float4*)(crow + 4) = o1;
    }
}

// ---------------------------------------------------------------------------
// Flash attention (fp32): grid (S/64, H, B), 256 threads.
// Each CTA: 64 q-rows of one (b,h). Stream 64-row KV tiles.
// Thread (tr,tc) owns a 4x4 sub-tile of scores/output.
// Online softmax state per row shared across the 16 threads of that row via
// shfl_xor reductions (lanes of a row group are contiguous 16 lanes).
// ---------------------------------------------------------------------------
#define SPAD 68   // row stride (floats) for 64-wide tiles, pad to dodge bank conflicts

extern __shared__ float sm_fa[];

__global__ __launch_bounds__(256) void flash_attn_kernel()
{
    float* Qs = sm_fa;                 // 64 x SPAD
    float* Ks = sm_fa + 64 * SPAD;     // 64 x SPAD
    float* Vs = sm_fa + 2 * 64 * SPAD; // 64 x SPAD
    float* Pt = sm_fa + 3 * 64 * SPAD; // 64 x SPAD (P transposed: [k][r])

    const int tid = threadIdx.x;
    const int qb = blockIdx.x * 64;
    const int h  = blockIdx.y;
    const int b  = blockIdx.z;

    const float* Qg = g_Q + (size_t)b * SEQ * EDIM + h * HDIM;
    const float* Kg = g_K + (size_t)b * SEQ * EDIM + h * HDIM;
    const float* Vg = g_V + (size_t)b * SEQ * EDIM + h * HDIM;
    float*       Og = g_O + (size_t)b * SEQ * EDIM + h * HDIM;

    // Load Q tile (64 rows x 64 cols), coalesced float4
#pragma unroll
    for (int it = 0; it < 4; it++) {
        int l = it * 256 + tid;
        int r = l >> 4;
        int c = (l & 15) * 4;
        *(float4*)&Qs[r * SPAD + c] = *(const float4*)&Qg[(size_t)(qb + r) * EDIM + c];
    }

    const int tr = (tid >> 4) * 4;   // row base within tile
    const int tc = (tid & 15) * 4;   // col base within tile

    float mrow[4], lrow[4], acc[4][4];
#pragma unroll
    for (int i = 0; i < 4; i++) {
        mrow[i] = -1e30f;
        lrow[i] = 0.f;
#pragma unroll
        for (int j = 0; j < 4; j++) acc[i][j] = 0.f;
    }
    __syncthreads();

    for (int kb = 0; kb < SEQ; kb += 64) {
        // Load K and V tiles
#pragma unroll
        for (int it = 0; it < 4; it++) {
            int l = it * 256 + tid;
            int r = l >> 4;
            int c = (l & 15) * 4;
            *(float4*)&Ks[r * SPAD + c] = *(const float4*)&Kg[(size_t)(kb + r) * EDIM + c];
            *(float4*)&Vs[r * SPAD + c] = *(const float4*)&Vg[(size_t)(kb + r) * EDIM + c];
        }
        __syncthreads();

        // Scores: s[i][j] = Q[tr+i] . K[tc+j]
        float s[4][4];
#pragma unroll
        for (int i = 0; i < 4; i++)
#pragma unroll
            for (int j = 0; j < 4; j++) s[i][j] = 0.f;

#pragma unroll
        for (int d = 0; d < 64; d += 4) {
            float4 q0 = *(float4*)&Qs[(tr + 0) * SPAD + d];
            float4 q1 = *(float4*)&Qs[(tr + 1) * SPAD + d];
            float4 q2 = *(float4*)&Qs[(tr + 2) * SPAD + d];
            float4 q3 = *(float4*)&Qs[(tr + 3) * SPAD + d];
            float4 k0 = *(float4*)&Ks[(tc + 0) * SPAD + d];
            float4 k1 = *(float4*)&Ks[(tc + 1) * SPAD + d];
            float4 k2 = *(float4*)&Ks[(tc + 2) * SPAD + d];
            float4 k3 = *(float4*)&Ks[(tc + 3) * SPAD + d];
            float4 qa[4] = {q0, q1, q2, q3};
            float4 ka[4] = {k0, k1, k2, k3};
#pragma unroll
            for (int i = 0; i < 4; i++)
#pragma unroll
                for (int j = 0; j < 4; j++) {
                    s[i][j] = fmaf(qa[i].x, ka[j].x, s[i][j]);
                    s[i][j] = fmaf(qa[i].y, ka[j].y, s[i][j]);
                    s[i][j] = fmaf(qa[i].z, ka[j].z, s[i][j]);
                    s[i][j] = fmaf(qa[i].w, ka[j].w, s[i][j]);
                }
        }

        // Online softmax per row (16 threads share a row; contiguous 16 lanes)
#pragma unroll
        for (int i = 0; i < 4; i++) {
#pragma unroll
            for (int j = 0; j < 4; j++) s[i][j] *= INV_SCALE;
            float mx = fmaxf(fmaxf(s[i][0], s[i][1]), fmaxf(s[i][2], s[i][3]));
#pragma unroll
            for (int off = 8; off >= 1; off >>= 1)
                mx = fmaxf(mx, __shfl_xor_sync(0xffffffffu, mx, off));
            float mnew = fmaxf(mrow[i], mx);
            float alpha = __expf(mrow[i] - mnew);
            mrow[i] = mnew;
            float ps = 0.f;
#pragma unroll
            for (int j = 0; j < 4; j++) {
                s[i][j] = __expf(s[i][j] - mnew);
                ps += s[i][j];
            }
#pragma unroll
            for (int off = 8; off >= 1; off >>= 1)
                ps += __shfl_xor_sync(0xffffffffu, ps, off);
            lrow[i] = lrow[i] * alpha + ps;
#pragma unroll
            for (int j = 0; j < 4; j++) acc[i][j] *= alpha;
        }

        // Stage P transposed: Pt[k][r] = p[r][k]
#pragma unroll
        for (int j = 0; j < 4; j++) {
            float4 pv = make_float4(s[0][j], s[1][j], s[2][j], s[3][j]);
            *(float4*)&Pt[(tc + j) * SPAD + tr] = pv;
        }
        __syncthreads();

        // PV: acc[i][j] += sum_k P[r_i][k] * V[k][c_j]
#pragma unroll 8
        for (int k = 0; k < 64; k++) {
            float4 pr = *(float4*)&Pt[k * SPAD + tr];
            float4 vv = *(float4*)&Vs[k * SPAD + tc];
            float pa[4] = {pr.x, pr.y, pr.z, pr.w};
            float va[4] = {vv.x, vv.y, vv.z, vv.w};
#pragma unroll
            for (int i = 0; i < 4; i++)
#pragma unroll
                for (int j = 0; j < 4; j++)
                    acc[i][j] = fmaf(pa[i], va[j], acc[i][j]);
        }
        __syncthreads();
    }

    // Epilogue: normalize and store
#pragma unroll
    for (int i = 0; i < 4; i++) {
        float inv = 1.f / lrow[i];
        float4 o = make_float4(acc[i][0] * inv, acc[i][1] * inv,
                               acc[i][2] * inv, acc[i][3] * inv);
        *(float4*)&Og[(size_t)(qb + tr + i) * EDIM + tc] = o;
    }
}

// ---------------------------------------------------------------------------
// Launch
// ---------------------------------------------------------------------------
extern "C" void kernel_launch(void* const* d_in, const int* in_sizes, int n_in,
                              void* d_out, int out_size)
{
    (void)in_sizes; (void)n_in; (void)out_size;
    const float* q  = (const float*)d_in[0];
    const float* k  = (const float*)d_in[1];
    const float* v  = (const float*)d_in[2];
    const float* Wq = (const float*)d_in[3];
    const float* Wk = (const float*)d_in[4];
    const float* Wv = (const float*)d_in[5];
    const float* Wo = (const float*)d_in[6];
    float* out = (float*)d_out;

    float *Qp, *Kp, *Vp, *Op;
    cudaGetSymbolAddress((void**)&Qp, g_Q);
    cudaGetSymbolAddress((void**)&Kp, g_K);
    cudaGetSymbolAddress((void**)&Vp, g_V);
    cudaGetSymbolAddress((void**)&Op, g_O);

    static int smem_set = 0;
    if (!smem_set) {
        cudaFuncSetAttribute(flash_attn_kernel,
                             cudaFuncAttributeMaxDynamicSharedMemorySize,
                             4 * 64 * SPAD * sizeof(float));
        smem_set = 1;
    }

    dim3 gemm_grid(EDIM / BN, MROWS / BM);  // (8, 32)
    sgemm_nt<<<gemm_grid, 256>>>(q, Wq, Qp, MROWS, EDIM, EDIM);
    sgemm_nt<<<gemm_grid, 256>>>(k, Wk, Kp, MROWS, EDIM, EDIM);
    sgemm_nt<<<gemm_grid, 256>>>(v, Wv, Vp, MROWS, EDIM, EDIM);

    dim3 fa_grid(SEQ / 64, NHEADS, BATCH);  // (32, 16, 2)
    flash_attn_kernel<<<fa_grid, 256, 4 * 64 * SPAD * sizeof(float)>>>();

    sgemm_nt<<<gemm_grid, 256>>>(Op, Wo, out, MROWS, EDIM, EDIM);
}

// round 3
// speedup vs baseline: 3.2708x; 3.2708x over previous
#include <cuda_runtime.h>
#include <cuda_bf16.h>
#include <cstdint>

// Problem constants
#define EDIM 1024
#define BATCH 2
#define SEQ 2048
#define NHEADS 16
#define HDIM 64
#define MROWS (BATCH * SEQ)          // 4096
#define QSCALE 0.125f                // 1/sqrt(64), exact power of two

// ---------------------------------------------------------------------------
// Scratch (allocation-free: static __device__ globals)
// ---------------------------------------------------------------------------
__device__ float g_Q[MROWS * EDIM];
__device__ float g_K[MROWS * EDIM];
__device__ float g_V[MROWS * EDIM];
__device__ float g_O[MROWS * EDIM];
__device__ __nv_bfloat16 g_ahi[MROWS * EDIM];
__device__ __nv_bfloat16 g_alo[MROWS * EDIM];
__device__ __nv_bfloat16 g_whi[EDIM * EDIM];
__device__ __nv_bfloat16 g_wlo[EDIM * EDIM];

// ---------------------------------------------------------------------------
// HMMA / ldmatrix primitives (portable sm_80+ ISA, works at compute_103)
// ---------------------------------------------------------------------------
__device__ __forceinline__ uint32_t smem_u32(const void* p) {
    uint32_t a;
    asm("{ .reg .u64 t; cvta.to.shared.u64 t, %1; cvt.u32.u64 %0, t; }"
        : "=r"(a) : "l"(p));
    return a;
}

#define LDSM_X4(r0, r1, r2, r3, addr) \
    asm volatile("ldmatrix.sync.aligned.m8n8.x4.shared.b16 {%0,%1,%2,%3}, [%4];" \
        : "=r"(r0), "=r"(r1), "=r"(r2), "=r"(r3) : "r"(addr))

#define LDSM_X2(r0, r1, addr) \
    asm volatile("ldmatrix.sync.aligned.m8n8.x2.shared.b16 {%0,%1}, [%2];" \
        : "=r"(r0), "=r"(r1) : "r"(addr))

#define LDSM_X2T(r0, r1, addr) \
    asm volatile("ldmatrix.sync.aligned.m8n8.x2.trans.shared.b16 {%0,%1}, [%2];" \
        : "=r"(r0), "=r"(r1) : "r"(addr))

__device__ __forceinline__ void mma_bf16(float* c, uint32_t a0, uint32_t a1,
                                         uint32_t a2, uint32_t a3,
                                         uint32_t b0, uint32_t b1) {
    asm volatile(
        "mma.sync.aligned.m16n8k16.row.col.f32.bf16.bf16.f32 "
        "{%0,%1,%2,%3}, {%4,%5,%6,%7}, {%8,%9}, {%0,%1,%2,%3};"
        : "+f"(c[0]), "+f"(c[1]), "+f"(c[2]), "+f"(c[3])
        : "r"(a0), "r"(a1), "r"(a2), "r"(a3), "r"(b0), "r"(b1));
}

__device__ __forceinline__ uint32_t pack_bf16(float x, float y) {
    __nv_bfloat162 t = __floats2bfloat162_rn(x, y);
    return *(uint32_t*)&t;
}

// Split (x,y) into bf16 hi pair + bf16 lo (residual) pair, packed.
__device__ __forceinline__ void split_pack2(float x, float y,
                                            uint32_t& hi, uint32_t& lo) {
    __nv_bfloat16 hx = __float2bfloat16(x);
    __nv_bfloat16 hy = __float2bfloat16(y);
    __nv_bfloat162 h2 = __halves2bfloat162(hx, hy);
    hi = *(uint32_t*)&h2;
    lo = pack_bf16(x - __bfloat162float(hx), y - __bfloat162float(hy));
}

// ---------------------------------------------------------------------------
// Split fp32 -> (bf16 hi, bf16 lo) arrays (for GEMM operands)
// ---------------------------------------------------------------------------
__global__ __launch_bounds__(256) void split_bf16_kernel(
    const float* __restrict__ x,
    __nv_bfloat16* __restrict__ hi,
    __nv_bfloat16* __restrict__ lo,
    int n)
{
    int i = (blockIdx.x * blockDim.x + threadIdx.x) * 4;
    if (i >= n) return;
    float4 v = *(const float4*)(x + i);
    uint32_t h01, l01, h23, l23;
    split_pack2(v.x, v.y, h01, l01);
    split_pack2(v.z, v.w, h23, l23);
    *(uint2*)(hi + i) = make_uint2(h01, h23);
    *(uint2*)(lo + i) = make_uint2(l01, l23);
}

// ---------------------------------------------------------------------------
// HMMA bf16x3 GEMM: C[M,N] = Ahi Whi^T + Alo Whi^T + Ahi Wlo^T  (fp32 out)
// CTA 128x128, BK=64, 256 threads = 8 warps, warp tile 64x32.
// Smem rows padded to 72 halves (144B) -> conflict-free ldmatrix.
// ---------------------------------------------------------------------------
#define GPAD 72
#define GTILE_HALVES (128 * GPAD)
#define GSMEM_BYTES (4 * GTILE_HALVES * 2)

__global__ __launch_bounds__(256) void hgemm_bf16x3(
    const __nv_bfloat16* __restrict__ Ahi, const __nv_bfloat16* __restrict__ Alo,
    const __nv_bfloat16* __restrict__ Whi, const __nv_bfloat16* __restrict__ Wlo,
    float* __restrict__ C, int M, int N, int K)
{
    extern __shared__ __nv_bfloat16 hsm[];
    __nv_bfloat16* sAhi = hsm;
    __nv_bfloat16* sAlo = hsm + GTILE_HALVES;
    __nv_bfloat16* sWhi = hsm + 2 * GTILE_HALVES;
    __nv_bfloat16* sWlo = hsm + 3 * GTILE_HALVES;

    const int tid = threadIdx.x;
    const int wid = tid >> 5;
    const int lane = tid & 31;
    const int bm = blockIdx.y * 128;
    const int bn = blockIdx.x * 128;
    const int moff = (wid >> 2) * 64;   // 0 or 64
    const int noff = (wid & 3) * 32;    // 0..96

    float acc[4][4][4];
#pragma unroll
    for (int mt = 0; mt < 4; mt++)
#pragma unroll
        for (int nt = 0; nt < 4; nt++)
#pragma unroll
            for (int r = 0; r < 4; r++) acc[mt][nt][r] = 0.f;

    const uint32_t aHiB = smem_u32(sAhi);
    const uint32_t aLoB = smem_u32(sAlo);
    const uint32_t wHiB = smem_u32(sWhi);
    const uint32_t wLoB = smem_u32(sWlo);

    // ldmatrix per-thread address offsets (bytes)
    const uint32_t a_off = ((moff + (lane & 15)) * GPAD + (lane >> 4) * 8) * 2;
    const uint32_t b_off = ((noff + (lane & 7)) * GPAD + ((lane >> 3) & 1) * 8) * 2;

    const int loadR = tid >> 1;          // 0..127 (row per 2 threads)
    const int loadC = (tid & 1) * 8;     // wait: 64 halves/row = 8 chunks of 8

    (void)loadR; (void)loadC;

    for (int t = 0; t < K / 64; t++) {
        __syncthreads();
        const int k0 = t * 64;
        // load 4 tiles of 128x64 halves; 8 chunks (of 8 halves) per row
#pragma unroll
        for (int it = 0; it < 4; it++) {
            int l = it * 256 + tid;       // 0..1023
            int r = l >> 3;
            int c8 = (l & 7) * 8;
            *(uint4*)(sAhi + r * GPAD + c8) = *(const uint4*)(Ahi + (size_t)(bm + r) * K + k0 + c8);
            *(uint4*)(sAlo + r * GPAD + c8) = *(const uint4*)(Alo + (size_t)(bm + r) * K + k0 + c8);
            *(uint4*)(sWhi + r * GPAD + c8) = *(const uint4*)(Whi + (size_t)(bn + r) * K + k0 + c8);
            *(uint4*)(sWlo + r * GPAD + c8) = *(const uint4*)(Wlo + (size_t)(bn + r) * K + k0 + c8);
        }
        __syncthreads();

#pragma unroll
        for (int ks = 0; ks < 4; ks++) {
            const uint32_t koff = ks * 16 * 2;
            uint32_t bhi[4][2], blo[4][2];
#pragma unroll
            for (int nt = 0; nt < 4; nt++) {
                LDSM_X2(bhi[nt][0], bhi[nt][1], wHiB + b_off + nt * (8 * GPAD * 2) + koff);
                LDSM_X2(blo[nt][0], blo[nt][1], wLoB + b_off + nt * (8 * GPAD * 2) + koff);
            }
#pragma unroll
            for (int mt = 0; mt < 4; mt++) {
                uint32_t ah0, ah1, ah2, ah3, al0, al1, al2, al3;
                LDSM_X4(ah0, ah1, ah2, ah3, aHiB + a_off + mt * (16 * GPAD * 2) + koff);
                LDSM_X4(al0, al1, al2, al3, aLoB + a_off + mt * (16 * GPAD * 2) + koff);
#pragma unroll
                for (int nt = 0; nt < 4; nt++) {
                    mma_bf16(acc[mt][nt], ah0, ah1, ah2, ah3, bhi[nt][0], bhi[nt][1]);
                    mma_bf16(acc[mt][nt], al0, al1, al2, al3, bhi[nt][0], bhi[nt][1]);
                    mma_bf16(acc[mt][nt], ah0, ah1, ah2, ah3, blo[nt][0], blo[nt][1]);
                }
            }
        }
    }

    // Epilogue
#pragma unroll
    for (int mt = 0; mt < 4; mt++) {
#pragma unroll
        for (int nt = 0; nt < 4; nt++) {
            int r0 = bm + moff + mt * 16 + (lane >> 2);
            int c0 = bn + noff + nt * 8 + (lane & 3) * 2;
            *(float2*)(C + (size_t)r0 * N + c0) = make_float2(acc[mt][nt][0], acc[mt][nt][1]);
            *(float2*)(C + (size_t)(r0 + 8) * N + c0) = make_float2(acc[mt][nt][2], acc[mt][nt][3]);
        }
    }
}

// ---------------------------------------------------------------------------
// Flash attention on HMMA (bf16x3 QK^T and PV, fp32 softmax)
// CTA: 128 q-rows of one (b,h); 8 warps; warp = 16 q-rows x 128-kv tile.
// ---------------------------------------------------------------------------
#define FPAD 72
#define FTILE_HALVES (128 * FPAD)
#define FSMEM_BYTES (6 * FTILE_HALVES * 2)

// Load a 128x64 fp32 tile (row stride EDIM), scale, split to bf16 hi/lo smem.
__device__ __forceinline__ void load_split_tile(
    const float* __restrict__ gsrc,
    __nv_bfloat16* __restrict__ shi, __nv_bfloat16* __restrict__ slo,
    float scale, int tid)
{
#pragma unroll
    for (int it = 0; it < 8; it++) {
        int l = it * 256 + tid;     // 0..2047
        int r = l >> 4;
        int c = (l & 15) * 4;
        float4 v = *(const float4*)(gsrc + (size_t)r * EDIM + c);
        v.x *= scale; v.y *= scale; v.z *= scale; v.w *= scale;
        uint32_t h01, l01, h23, l23;
        split_pack2(v.x, v.y, h01, l01);
        split_pack2(v.z, v.w, h23, l23);
        *(uint2*)(shi + r * FPAD + c) = make_uint2(h01, h23);
        *(uint2*)(slo + r * FPAD + c) = make_uint2(l01, l23);
    }
}

__global__ __launch_bounds__(256) void flash_hmma()
{
    extern __shared__ __nv_bfloat16 fsm[];
    __nv_bfloat16* sQhi = fsm;
    __nv_bfloat16* sQlo = fsm + FTILE_HALVES;
    __nv_bfloat16* sKhi = fsm + 2 * FTILE_HALVES;
    __nv_bfloat16* sKlo = fsm + 3 * FTILE_HALVES;
    __nv_bfloat16* sVhi = fsm + 4 * FTILE_HALVES;
    __nv_bfloat16* sVlo = fsm + 5 * FTILE_HALVES;

    const int tid = threadIdx.x;
    const int wid = tid >> 5;
    const int lane = tid & 31;
    const int qb = blockIdx.x * 128;
    const int h = blockIdx.y;
    const int b = blockIdx.z;

    const float* Qg = g_Q + ((size_t)b * SEQ + qb) * EDIM + h * HDIM;
    const float* Kg = g_K + (size_t)b * SEQ * EDIM + h * HDIM;
    const float* Vg = g_V + (size_t)b * SEQ * EDIM + h * HDIM;

    // Q tile, scaled by 1/sqrt(D) (exact pow2 -> folded before split)
    load_split_tile(Qg, sQhi, sQlo, QSCALE, tid);
    __syncthreads();

    const uint32_t qHiB = smem_u32(sQhi);
    const uint32_t qLoB = smem_u32(sQlo);
    const uint32_t kHiB = smem_u32(sKhi);
    const uint32_t kLoB = smem_u32(sKlo);
    const uint32_t vHiB = smem_u32(sVhi);
    const uint32_t vLoB = smem_u32(sVlo);

    // ldmatrix per-thread byte offsets
    const uint32_t a_off  = ((wid * 16 + (lane & 15)) * FPAD + (lane >> 4) * 8) * 2;
    const uint32_t bk_off = ((lane & 7) * FPAD + ((lane >> 3) & 1) * 8) * 2;
    const uint32_t bv_off = (((lane & 7) + ((lane >> 3) & 1) * 8) * FPAD) * 2;

    float o[8][4];
#pragma unroll
    for (int nt = 0; nt < 8; nt++)
#pragma unroll
        for (int r = 0; r < 4; r++) o[nt][r] = 0.f;
    float m0 = -1e30f, m1 = -1e30f, l0 = 0.f, l1 = 0.f;

    for (int kb = 0; kb < SEQ; kb += 128) {
        __syncthreads();
        load_split_tile(Kg + (size_t)kb * EDIM, sKhi, sKlo, 1.f, tid);
        load_split_tile(Vg + (size_t)kb * EDIM, sVhi, sVlo, 1.f, tid);
        __syncthreads();

        // --- S = Qhi Khi^T + Qlo Khi^T + Qhi Klo^T ---
        float s[16][4];
#pragma unroll
        for (int nt = 0; nt < 16; nt++)
#pragma unroll
            for (int r = 0; r < 4; r++) s[nt][r] = 0.f;

#pragma unroll
        for (int ks = 0; ks < 4; ks++) {
            const uint32_t koff = ks * 16 * 2;
            uint32_t qh0, qh1, qh2, qh3, ql0, ql1, ql2, ql3;
            LDSM_X4(qh0, qh1, qh2, qh3, qHiB + a_off + koff);
            LDSM_X4(ql0, ql1, ql2, ql3, qLoB + a_off + koff);
#pragma unroll
            for (int nt = 0; nt < 16; nt++) {
                uint32_t bh0, bh1, bl0, bl1;
                const uint32_t boff = bk_off + nt * (8 * FPAD * 2) + koff;
                LDSM_X2(bh0, bh1, kHiB + boff);
                mma_bf16(s[nt], qh0, qh1, qh2, qh3, bh0, bh1);
                mma_bf16(s[nt], ql0, ql1, ql2, ql3, bh0, bh1);
                LDSM_X2(bl0, bl1, kLoB + boff);
                mma_bf16(s[nt], qh0, qh1, qh2, qh3, bl0, bl1);
            }
        }

        // --- online softmax (rows r0 = regs 0,1 ; r1 = regs 2,3) ---
        float mx0 = -1e30f, mx1 = -1e30f;
#pragma unroll
        for (int nt = 0; nt < 16; nt++) {
            mx0 = fmaxf(mx0, fmaxf(s[nt][0], s[nt][1]));
            mx1 = fmaxf(mx1, fmaxf(s[nt][2], s[nt][3]));
        }
        mx0 = fmaxf(mx0, __shfl_xor_sync(0xffffffffu, mx0, 1));
        mx0 = fmaxf(mx0, __shfl_xor_sync(0xffffffffu, mx0, 2));
        mx1 = fmaxf(mx1, __shfl_xor_sync(0xffffffffu, mx1, 1));
        mx1 = fmaxf(mx1, __shfl_xor_sync(0xffffffffu, mx1, 2));

        float mn0 = fmaxf(m0, mx0), mn1 = fmaxf(m1, mx1);
        float al0 = __expf(m0 - mn0), al1 = __expf(m1 - mn1);
        m0 = mn0; m1 = mn1;

        float sum0 = 0.f, sum1 = 0.f;
#pragma unroll
        for (int nt = 0; nt < 16; nt++) {
            s[nt][0] = __expf(s[nt][0] - mn0);
            s[nt][1] = __expf(s[nt][1] - mn0);
            s[nt][2] = __expf(s[nt][2] - mn1);
            s[nt][3] = __expf(s[nt][3] - mn1);
            sum0 += s[nt][0] + s[nt][1];
            sum1 += s[nt][2] + s[nt][3];
        }
        sum0 += __shfl_xor_sync(0xffffffffu, sum0, 1);
        sum0 += __shfl_xor_sync(0xffffffffu, sum0, 2);
        sum1 += __shfl_xor_sync(0xffffffffu, sum1, 1);
        sum1 += __shfl_xor_sync(0xffffffffu, sum1, 2);
        l0 = l0 * al0 + sum0;
        l1 = l1 * al1 + sum1;

#pragma unroll
        for (int nt = 0; nt < 8; nt++) {
            o[nt][0] *= al0; o[nt][1] *= al0;
            o[nt][2] *= al1; o[nt][3] *= al1;
        }

        // --- O += Phi Vhi + Plo Vhi + Phi Vlo ---
#pragma unroll
        for (int kt = 0; kt < 8; kt++) {
            uint32_t ph[4], pl[4];
            split_pack2(s[2 * kt][0],     s[2 * kt][1],     ph[0], pl[0]);
            split_pack2(s[2 * kt][2],     s[2 * kt][3],     ph[1], pl[1]);
            split_pack2(s[2 * kt + 1][0], s[2 * kt + 1][1], ph[2], pl[2]);
            split_pack2(s[2 * kt + 1][2], s[2 * kt + 1][3], ph[3], pl[3]);
#pragma unroll
            for (int nt = 0; nt < 8; nt++) {
                const uint32_t voff = bv_off + kt * (16 * FPAD * 2) + nt * 8 * 2;
                uint32_t vh0, vh1, vl0, vl1;
                LDSM_X2T(vh0, vh1, vHiB + voff);
                mma_bf16(o[nt], ph[0], ph[1], ph[2], ph[3], vh0, vh1);
                mma_bf16(o[nt], pl[0], pl[1], pl[2], pl[3], vh0, vh1);
                LDSM_X2T(vl0, vl1, vLoB + voff);
                mma_bf16(o[nt], ph[0], ph[1], ph[2], ph[3], vl0, vl1);
            }
        }
    }

    // Epilogue: normalize, store fp32
    const int r0 = qb + wid * 16 + (lane >> 2);
    float inv0 = 1.f / l0, inv1 = 1.f / l1;
    float* Orow = g_O + ((size_t)b * SEQ + r0) * EDIM + h * HDIM;
#pragma unroll
    for (int nt = 0; nt < 8; nt++) {
        int c = nt * 8 + (lane & 3) * 2;
        *(float2*)(Orow + c) = make_float2(o[nt][0] * inv0, o[nt][1] * inv0);
        *(float2*)(Orow + (size_t)8 * EDIM + c) = make_float2(o[nt][2] * inv1, o[nt][3] * inv1);
    }
}

// ---------------------------------------------------------------------------
// Launch
// ---------------------------------------------------------------------------
extern "C" void kernel_launch(void* const* d_in, const int* in_sizes, int n_in,
                              void* d_out, int out_size)
{
    (void)in_sizes; (void)n_in; (void)out_size;
    const float* q  = (const float*)d_in[0];
    const float* k  = (const float*)d_in[1];
    const float* v  = (const float*)d_in[2];
    const float* Wq = (const float*)d_in[3];
    const float* Wk = (const float*)d_in[4];
    const float* Wv = (const float*)d_in[5];
    const float* Wo = (const float*)d_in[6];
    float* out = (float*)d_out;

    float *Qp, *Kp, *Vp, *Op;
    __nv_bfloat16 *ahi, *alo, *whi, *wlo;
    cudaGetSymbolAddress((void**)&Qp, g_Q);
    cudaGetSymbolAddress((void**)&Kp, g_K);
    cudaGetSymbolAddress((void**)&Vp, g_V);
    cudaGetSymbolAddress((void**)&Op, g_O);
    cudaGetSymbolAddress((void**)&ahi, g_ahi);
    cudaGetSymbolAddress((void**)&alo, g_alo);
    cudaGetSymbolAddress((void**)&whi, g_whi);
    cudaGetSymbolAddress((void**)&wlo, g_wlo);

    static int attr_set = 0;
    if (!attr_set) {
        cudaFuncSetAttribute(hgemm_bf16x3,
                             cudaFuncAttributeMaxDynamicSharedMemorySize, GSMEM_BYTES);
        cudaFuncSetAttribute(flash_hmma,
                             cudaFuncAttributeMaxDynamicSharedMemorySize, FSMEM_BYTES);
        attr_set = 1;
    }

    const int nA = MROWS * EDIM;   // 4M elements
    const int nW = EDIM * EDIM;    // 1M elements
    dim3 ggrid(EDIM / 128, MROWS / 128);   // (8, 32)

    // Q projection
    split_bf16_kernel<<<nA / 1024, 256>>>(q, ahi, alo, nA);
    split_bf16_kernel<<<nW / 1024, 256>>>(Wq, whi, wlo, nW);
    hgemm_bf16x3<<<ggrid, 256, GSMEM_BYTES>>>(ahi, alo, whi, wlo, Qp, MROWS, EDIM, EDIM);
    // K projection
    split_bf16_kernel<<<nA / 1024, 256>>>(k, ahi, alo, nA);
    split_bf16_kernel<<<nW / 1024, 256>>>(Wk, whi, wlo, nW);
    hgemm_bf16x3<<<ggrid, 256, GSMEM_BYTES>>>(ahi, alo, whi, wlo, Kp, MROWS, EDIM, EDIM);
    // V projection
    split_bf16_kernel<<<nA / 1024, 256>>>(v, ahi, alo, nA);
    split_bf16_kernel<<<nW / 1024, 256>>>(Wv, whi, wlo, nW);
    hgemm_bf16x3<<<ggrid, 256, GSMEM_BYTES>>>(ahi, alo, whi, wlo, Vp, MROWS, EDIM, EDIM);

    // Fused flash attention
    dim3 fgrid(SEQ / 128, NHEADS, BATCH);  // (16, 16, 2)
    flash_hmma<<<fgrid, 256, FSMEM_BYTES>>>();

    // Output projection
    split_bf16_kernel<<<nA / 1024, 256>>>(Op, ahi, alo, nA);
    split_bf16_kernel<<<nW / 1024, 256>>>(Wo, whi, wlo, nW);
    hgemm_bf16x3<<<ggrid, 256, GSMEM_BYTES>>>(ahi, alo, whi, wlo, out, MROWS, EDIM, EDIM);
}